// round 4
// baseline (speedup 1.0000x reference)
#include <cuda_runtime.h>
#include <math.h>

#define NN 10000
#define EE 320000
#define EP (EE + NN)
#define HH 4
#define CC 128
#define HC 512
#define INC 256

// ---------------- scratch (device globals, never addressed from host) ----------------
__device__ float g_xl[NN * HC];
__device__ float g_xr[NN * HC];
__device__ float g_h[NN * CC];
__device__ int g_deg[NN];
__device__ int g_off[NN + 1];
__device__ int g_cur[NN];
__device__ int g_src[EP];
__device__ int g_eid[EP];
__device__ int g_is64;

// edge index fetch that works for both int32 and int64 payloads
__device__ __forceinline__ int edge_at(const void* ei, int idx) {
    if (g_is64) return (int)((const long long*)ei)[idx];
    return ((const int*)ei)[idx];
}

// ---------------- dtype probe ----------------
__global__ void detect_dtype(const unsigned int* __restrict__ ei) {
    // If data is int64 with values in [0,NN), every odd 32-bit word (high half)
    // is 0 and every even word is < NN. If data is int32 indices, odd words are
    // themselves random indices (nonzero w.h.p.).
    int looks64 = 1;
    for (int i = 0; i < 128; i++) {
        if (ei[2 * i + 1] != 0u) looks64 = 0;
        if (ei[2 * i] >= (unsigned)NN) looks64 = 0;
    }
    g_is64 = looks64;
}

// ---------------- CSR build ----------------
__global__ void init_deg() {
    int i = blockIdx.x * blockDim.x + threadIdx.x;
    if (i < NN) g_deg[i] = 1;  // self-loop counted up front
}

__global__ void count_deg(const void* __restrict__ ei) {
    int e = blockIdx.x * blockDim.x + threadIdx.x;
    if (e < EE) {
        int d = edge_at(ei, EE + e);
        atomicAdd(&g_deg[d], 1);
    }
}

__global__ void scan_off() {
    __shared__ int ss[1024];
    int t = threadIdx.x;
    const int CH = (NN + 1023) / 1024;  // 10
    int base = t * CH;
    int s = 0;
    for (int i = 0; i < CH; i++) {
        int idx = base + i;
        if (idx < NN) s += g_deg[idx];
    }
    ss[t] = s;
    __syncthreads();
    for (int o = 1; o < 1024; o <<= 1) {
        int v = (t >= o) ? ss[t - o] : 0;
        __syncthreads();
        ss[t] += v;
        __syncthreads();
    }
    int run = (t == 0) ? 0 : ss[t - 1];
    for (int i = 0; i < CH; i++) {
        int idx = base + i;
        if (idx < NN) {
            g_off[idx] = run;
            g_cur[idx] = run;
            run += g_deg[idx];
        }
    }
    if (t == 1023) g_off[NN] = ss[1023];
}

__global__ void fill_csr(const void* __restrict__ ei) {
    int e = blockIdx.x * blockDim.x + threadIdx.x;
    if (e >= EP) return;
    int s, d;
    if (e < EE) {
        s = edge_at(ei, e);
        d = edge_at(ei, EE + e);
    } else {
        s = e - EE;
        d = s;
    }
    int pos = atomicAdd(&g_cur[d], 1);
    g_src[pos] = s;
    g_eid[pos] = e;
}

// ---------------- SGEMM: C[M,HC] = A[M,K] * B[K,HC] ----------------
// ASEL: 0 -> external A (arg), 1 -> g_h.  DSEL: 0 -> g_xl, 1 -> g_xr.
// 128x128 tile, BK=8, 256 threads, 8x8 per thread.
template <int ASEL, int DSEL, int K>
__global__ void __launch_bounds__(256) sgemm(const float* __restrict__ Aext,
                                             const float* __restrict__ B) {
    const int BM = 128, BN = 128, BK = 8;
    const float* A = (ASEL == 0) ? Aext : (const float*)g_h;
    float* C = (DSEL == 0) ? g_xl : g_xr;
    const int Nc = HC;
    __shared__ float As[BK][BM];
    __shared__ float Bs[BK][BN];
    int t = threadIdx.x;
    int bm = blockIdx.y * BM, bn = blockIdx.x * BN;
    int ty = t / 16, tx = t % 16;

    float acc[8][8];
#pragma unroll
    for (int i = 0; i < 8; i++)
#pragma unroll
        for (int j = 0; j < 8; j++) acc[i][j] = 0.f;

    int arow = t >> 1, acol = (t & 1) * 4;
    int brow = t >> 5, bcol = (t & 31) * 4;

    for (int k0 = 0; k0 < K; k0 += BK) {
        float4 av = make_float4(0.f, 0.f, 0.f, 0.f);
        int gr = bm + arow;
        if (gr < NN) av = *(const float4*)(A + (size_t)gr * K + k0 + acol);
        As[acol + 0][arow] = av.x;
        As[acol + 1][arow] = av.y;
        As[acol + 2][arow] = av.z;
        As[acol + 3][arow] = av.w;
        float4 bv = *(const float4*)(B + (size_t)(k0 + brow) * Nc + bn + bcol);
        *(float4*)&Bs[brow][bcol] = bv;
        __syncthreads();
#pragma unroll
        for (int k = 0; k < BK; k++) {
            float a[8], b[8];
            *(float4*)(a + 0) = *(float4*)&As[k][ty * 8];
            *(float4*)(a + 4) = *(float4*)&As[k][ty * 8 + 4];
            *(float4*)(b + 0) = *(float4*)&Bs[k][tx * 8];
            *(float4*)(b + 4) = *(float4*)&Bs[k][tx * 8 + 4];
#pragma unroll
            for (int i = 0; i < 8; i++)
#pragma unroll
                for (int j = 0; j < 8; j++) acc[i][j] += a[i] * b[j];
        }
        __syncthreads();
    }
#pragma unroll
    for (int i = 0; i < 8; i++) {
        int gr = bm + ty * 8 + i;
        if (gr < NN) {
            float* cp = C + (size_t)gr * Nc + bn + tx * 8;
            *(float4*)(cp + 0) = make_float4(acc[i][0], acc[i][1], acc[i][2], acc[i][3]);
            *(float4*)(cp + 4) = make_float4(acc[i][4], acc[i][5], acc[i][6], acc[i][7]);
        }
    }
}

// ---------------- edge / softmax / aggregate kernel ----------------
// block = dst node, warp = head, online softmax; xl rows read exactly once.
template <int LAYER>
__global__ void __launch_bounds__(128) edge_attn(
    const float* __restrict__ att, const float* __restrict__ bias,
    const float* __restrict__ bng, const float* __restrict__ bnb,
    const float* __restrict__ bnm, const float* __restrict__ bnv,
    const float* __restrict__ Wlin, const float* __restrict__ blin,
    float* __restrict__ alpha, float* __restrict__ nodeout) {
    const float* xl = (const float*)g_xl;
    const float* xr = (const float*)g_xr;
    int i = blockIdx.x, t = threadIdx.x;
    int h = t >> 5, lane = t & 31;
    int start = g_off[i], end = g_off[i + 1];
    int col = h * CC + lane * 4;

    const float4 xr4 = *(const float4*)(xr + (size_t)i * HC + col);
    const float4 a4 = *(const float4*)(att + col);

    float m = -3.4e38f, denom = 0.f;
    float4 acc = make_float4(0.f, 0.f, 0.f, 0.f);

    for (int e = start; e < end; e++) {
        int s = g_src[e];
        float4 xv = *(const float4*)(xl + (size_t)s * HC + col);
        float t0 = xv.x + xr4.x;
        float t1 = xv.y + xr4.y;
        float t2 = xv.z + xr4.z;
        float t3 = xv.w + xr4.w;
        t0 = t0 > 0.f ? t0 : 0.2f * t0;
        t1 = t1 > 0.f ? t1 : 0.2f * t1;
        t2 = t2 > 0.f ? t2 : 0.2f * t2;
        t3 = t3 > 0.f ? t3 : 0.2f * t3;
        float p = t0 * a4.x + t1 * a4.y + t2 * a4.z + t3 * a4.w;
#pragma unroll
        for (int o = 16; o; o >>= 1) p += __shfl_xor_sync(0xffffffffu, p, o);
        if (lane == 0) alpha[(size_t)g_eid[e] * HH + h] = p;  // park raw logit
        if (p > m) {
            float sc = __expf(m - p);
            denom *= sc;
            acc.x *= sc; acc.y *= sc; acc.z *= sc; acc.w *= sc;
            m = p;
        }
        float ex = __expf(p - m);
        denom += ex;
        acc.x += ex * xv.x;
        acc.y += ex * xv.y;
        acc.z += ex * xv.z;
        acc.w += ex * xv.w;
    }
    float inv = 1.f / (denom + 1e-16f);
    __syncwarp();
    // finalize alphas (raw logit -> softmax weight), lanes strided over edges
    for (int e = start + lane; e < end; e += 32) {
        size_t idx = (size_t)g_eid[e] * HH + h;
        alpha[idx] = __expf(alpha[idx] - m) * inv;
    }

    // combine heads (mean), bias, BN, ReLU
    __shared__ float red[HC];
    red[col + 0] = acc.x * inv;
    red[col + 1] = acc.y * inv;
    red[col + 2] = acc.z * inv;
    red[col + 3] = acc.w * inv;
    __syncthreads();
    float sum = (red[t] + red[CC + t] + red[2 * CC + t] + red[3 * CC + t]) * 0.25f + bias[t];
    float scale = bng[t] * rsqrtf(bnv[t] + 1e-5f);
    float y = (sum - bnm[t]) * scale + bnb[t];
    y = fmaxf(y, 0.f);

    if (LAYER == 1) {
        g_h[(size_t)i * CC + t] = y;
    } else {
        __shared__ float rr[CC];
        rr[t] = y * Wlin[t];
        __syncthreads();
#pragma unroll
        for (int o = 64; o; o >>= 1) {
            if (t < o) rr[t] += rr[t + o];
            __syncthreads();
        }
        if (t == 0) {
            float z = fmaxf(rr[0] + blin[0], 0.f);
            nodeout[i] = 1.f / (1.f + __expf(-z));
        }
    }
}

// ---------------- launch ----------------
extern "C" void kernel_launch(void* const* d_in, const int* in_sizes, int n_in,
                              void* d_out, int out_size) {
    const float* x = (const float*)d_in[0];
    const void* ei = d_in[1];
    const float* Wl1 = (const float*)d_in[2];
    const float* Wr1 = (const float*)d_in[3];
    const float* att1 = (const float*)d_in[4];
    const float* b1 = (const float*)d_in[5];
    const float* Wl2 = (const float*)d_in[6];
    const float* Wr2 = (const float*)d_in[7];
    const float* att2 = (const float*)d_in[8];
    const float* b2 = (const float*)d_in[9];
    const float* g1 = (const float*)d_in[10];
    const float* be1 = (const float*)d_in[11];
    const float* m1 = (const float*)d_in[12];
    const float* v1 = (const float*)d_in[13];
    const float* g2 = (const float*)d_in[14];
    const float* be2 = (const float*)d_in[15];
    const float* m2 = (const float*)d_in[16];
    const float* v2 = (const float*)d_in[17];
    const float* Wlin = (const float*)d_in[18];
    const float* blin = (const float*)d_in[19];

    float* out = (float*)d_out;
    float* alpha1 = out + NN;
    float* alpha2 = alpha1 + (size_t)EP * HH;

    detect_dtype<<<1, 1>>>((const unsigned int*)ei);
    init_deg<<<(NN + 255) / 256, 256>>>();
    count_deg<<<(EE + 255) / 256, 256>>>(ei);
    scan_off<<<1, 1024>>>();
    fill_csr<<<(EP + 255) / 256, 256>>>(ei);

    dim3 gg(HC / 128, (NN + 127) / 128);
    sgemm<0, 0, INC><<<gg, 256>>>(x, Wl1);
    sgemm<0, 1, INC><<<gg, 256>>>(x, Wr1);
    edge_attn<1><<<NN, 128>>>(att1, b1, g1, be1, m1, v1,
                              nullptr, nullptr, alpha1, nullptr);
    sgemm<1, 0, CC><<<gg, 256>>>(nullptr, Wl2);
    sgemm<1, 1, CC><<<gg, 256>>>(nullptr, Wr2);
    edge_attn<2><<<NN, 128>>>(att2, b2, g2, be2, m2, v2,
                              Wlin, blin, alpha2, out);
}

// round 5
// speedup vs baseline: 1.1600x; 1.1600x over previous
#include <cuda_runtime.h>
#include <math.h>

#define NN 10000
#define EE 320000
#define EP (EE + NN)
#define HH 4
#define CC 128
#define HC 512
#define INC 256

// ---------------- scratch (device globals, never addressed from host) ----------------
__device__ float g_xl[NN * HC];
__device__ float g_xr[NN * HC];
__device__ float g_h[NN * CC];
__device__ int g_deg[NN];
__device__ int g_off[NN + 1];
__device__ int g_cur[NN];
__device__ int g_src[EP];
__device__ int g_eid[EP];
__device__ int g_is64;

// edge index fetch that works for both int32 and int64 payloads
__device__ __forceinline__ int edge_at(const void* ei, int idx) {
    if (g_is64) return (int)((const long long*)ei)[idx];
    return ((const int*)ei)[idx];
}

// ---------------- dtype probe ----------------
__global__ void detect_dtype(const unsigned int* __restrict__ ei) {
    int looks64 = 1;
    for (int i = 0; i < 128; i++) {
        if (ei[2 * i + 1] != 0u) looks64 = 0;
        if (ei[2 * i] >= (unsigned)NN) looks64 = 0;
    }
    g_is64 = looks64;
}

// ---------------- CSR build ----------------
__global__ void init_deg() {
    int i = blockIdx.x * blockDim.x + threadIdx.x;
    if (i < NN) g_deg[i] = 1;
}

__global__ void count_deg(const void* __restrict__ ei) {
    int e = blockIdx.x * blockDim.x + threadIdx.x;
    if (e < EE) {
        int d = edge_at(ei, EE + e);
        atomicAdd(&g_deg[d], 1);
    }
}

__global__ void scan_off() {
    __shared__ int ss[1024];
    int t = threadIdx.x;
    const int CH = (NN + 1023) / 1024;
    int base = t * CH;
    int s = 0;
    for (int i = 0; i < CH; i++) {
        int idx = base + i;
        if (idx < NN) s += g_deg[idx];
    }
    ss[t] = s;
    __syncthreads();
    for (int o = 1; o < 1024; o <<= 1) {
        int v = (t >= o) ? ss[t - o] : 0;
        __syncthreads();
        ss[t] += v;
        __syncthreads();
    }
    int run = (t == 0) ? 0 : ss[t - 1];
    for (int i = 0; i < CH; i++) {
        int idx = base + i;
        if (idx < NN) {
            g_off[idx] = run;
            g_cur[idx] = run;
            run += g_deg[idx];
        }
    }
    if (t == 1023) g_off[NN] = ss[1023];
}

__global__ void fill_csr(const void* __restrict__ ei) {
    int e = blockIdx.x * blockDim.x + threadIdx.x;
    if (e >= EP) return;
    int s, d;
    if (e < EE) {
        s = edge_at(ei, e);
        d = edge_at(ei, EE + e);
    } else {
        s = e - EE;
        d = s;
    }
    int pos = atomicAdd(&g_cur[d], 1);
    g_src[pos] = s;
    g_eid[pos] = e;
}

// ---------------- 3xTF32 tensor-core GEMM ----------------
// C[M,HC] = A[M,K] * B[K,HC], fp32-accurate via hi/lo tf32 split.
// BM=128, BN=64, BK=16, 256 threads (8 warps: 4 in M x 2 in N, 32x32 per warp).
// blockIdx.z selects (B0 -> g_xl) vs (B1 -> g_xr).

__device__ __forceinline__ unsigned tf32_of(float v) {
    unsigned r;
    asm("cvt.rna.tf32.f32 %0, %1;" : "=r"(r) : "f"(v));
    return r;
}

__device__ __forceinline__ void mma8(float* d, const unsigned* a, const unsigned* b) {
    asm volatile(
        "mma.sync.aligned.m16n8k8.row.col.f32.tf32.tf32.f32 "
        "{%0,%1,%2,%3}, {%4,%5,%6,%7}, {%8,%9}, {%0,%1,%2,%3};"
        : "+f"(d[0]), "+f"(d[1]), "+f"(d[2]), "+f"(d[3])
        : "r"(a[0]), "r"(a[1]), "r"(a[2]), "r"(a[3]), "r"(b[0]), "r"(b[1]));
}

template <int ASEL, int K>
__global__ void __launch_bounds__(256) gemm_tf32(const float* __restrict__ Aext,
                                                 const float* __restrict__ B0,
                                                 const float* __restrict__ B1) {
    const float* A = (ASEL == 0) ? Aext : (const float*)g_h;
    const float* B = blockIdx.z ? B1 : B0;
    float* C = blockIdx.z ? g_xr : g_xl;

    __shared__ float As_hi[16][132], As_lo[16][132];
    __shared__ float Bs_hi[16][68], Bs_lo[16][68];

    int t = threadIdx.x;
    int lane = t & 31, wid = t >> 5;
    int wm = wid & 3, wn = wid >> 2;          // 4 warps in M, 2 in N
    int tg = lane >> 2, tq = lane & 3;
    int bm = blockIdx.y * 128, bn = blockIdx.x * 64;

    float acc[2][4][4];
#pragma unroll
    for (int mt = 0; mt < 2; mt++)
#pragma unroll
        for (int nt = 0; nt < 4; nt++)
#pragma unroll
            for (int j = 0; j < 4; j++) acc[mt][nt][j] = 0.f;

    for (int k0 = 0; k0 < K; k0 += 16) {
        // A tile: 128 rows x 16 cols (transposed store, hi/lo split)
#pragma unroll
        for (int i = 0; i < 2; i++) {
            int s = t + i * 256;
            int r = s >> 2, c4 = (s & 3) * 4;
            float4 v = make_float4(0.f, 0.f, 0.f, 0.f);
            int gr = bm + r;
            if (gr < NN) v = *(const float4*)(A + (size_t)gr * K + k0 + c4);
            float vv[4] = {v.x, v.y, v.z, v.w};
#pragma unroll
            for (int j = 0; j < 4; j++) {
                unsigned hi = tf32_of(vv[j]);
                float hif = __uint_as_float(hi);
                unsigned lo = tf32_of(vv[j] - hif);
                As_hi[c4 + j][r] = hif;
                As_lo[c4 + j][r] = __uint_as_float(lo);
            }
        }
        // B tile: 16 rows x 64 cols
        {
            int r = t >> 4, c = (t & 15) * 4;
            float4 v = *(const float4*)(B + (size_t)(k0 + r) * HC + bn + c);
            float vv[4] = {v.x, v.y, v.z, v.w};
#pragma unroll
            for (int j = 0; j < 4; j++) {
                unsigned hi = tf32_of(vv[j]);
                float hif = __uint_as_float(hi);
                unsigned lo = tf32_of(vv[j] - hif);
                Bs_hi[r][c + j] = hif;
                Bs_lo[r][c + j] = __uint_as_float(lo);
            }
        }
        __syncthreads();

#pragma unroll
        for (int ks = 0; ks < 2; ks++) {
            int kk = ks * 8;
            unsigned ah[2][4], al[2][4], bh[4][2], bl[4][2];
#pragma unroll
            for (int mt = 0; mt < 2; mt++) {
                int rb = wm * 32 + mt * 16;
                ah[mt][0] = __float_as_uint(As_hi[kk + tq][rb + tg]);
                ah[mt][1] = __float_as_uint(As_hi[kk + tq][rb + tg + 8]);
                ah[mt][2] = __float_as_uint(As_hi[kk + tq + 4][rb + tg]);
                ah[mt][3] = __float_as_uint(As_hi[kk + tq + 4][rb + tg + 8]);
                al[mt][0] = __float_as_uint(As_lo[kk + tq][rb + tg]);
                al[mt][1] = __float_as_uint(As_lo[kk + tq][rb + tg + 8]);
                al[mt][2] = __float_as_uint(As_lo[kk + tq + 4][rb + tg]);
                al[mt][3] = __float_as_uint(As_lo[kk + tq + 4][rb + tg + 8]);
            }
#pragma unroll
            for (int nt = 0; nt < 4; nt++) {
                int cb = wn * 32 + nt * 8;
                bh[nt][0] = __float_as_uint(Bs_hi[kk + tq][cb + tg]);
                bh[nt][1] = __float_as_uint(Bs_hi[kk + tq + 4][cb + tg]);
                bl[nt][0] = __float_as_uint(Bs_lo[kk + tq][cb + tg]);
                bl[nt][1] = __float_as_uint(Bs_lo[kk + tq + 4][cb + tg]);
            }
#pragma unroll
            for (int mt = 0; mt < 2; mt++)
#pragma unroll
                for (int nt = 0; nt < 4; nt++) {
                    mma8(acc[mt][nt], ah[mt], bh[nt]);   // hi*hi
                    mma8(acc[mt][nt], ah[mt], bl[nt]);   // hi*lo
                    mma8(acc[mt][nt], al[mt], bh[nt]);   // lo*hi
                }
        }
        __syncthreads();
    }

    // epilogue
#pragma unroll
    for (int mt = 0; mt < 2; mt++)
#pragma unroll
        for (int nt = 0; nt < 4; nt++) {
            int row = bm + wm * 32 + mt * 16 + tg;
            int col = bn + wn * 32 + nt * 8 + 2 * tq;
            if (row < NN)
                *(float2*)(C + (size_t)row * HC + col) =
                    make_float2(acc[mt][nt][0], acc[mt][nt][1]);
            if (row + 8 < NN)
                *(float2*)(C + (size_t)(row + 8) * HC + col) =
                    make_float2(acc[mt][nt][2], acc[mt][nt][3]);
        }
}

// ---------------- edge / softmax / aggregate kernel ----------------
template <int LAYER>
__global__ void __launch_bounds__(128) edge_attn(
    const float* __restrict__ att, const float* __restrict__ bias,
    const float* __restrict__ bng, const float* __restrict__ bnb,
    const float* __restrict__ bnm, const float* __restrict__ bnv,
    const float* __restrict__ Wlin, const float* __restrict__ blin,
    float* __restrict__ alpha, float* __restrict__ nodeout) {
    const float* xl = (const float*)g_xl;
    const float* xr = (const float*)g_xr;
    int i = blockIdx.x, t = threadIdx.x;
    int h = t >> 5, lane = t & 31;
    int start = g_off[i], end = g_off[i + 1];
    int col = h * CC + lane * 4;

    const float4 xr4 = *(const float4*)(xr + (size_t)i * HC + col);
    const float4 a4 = *(const float4*)(att + col);

    float m = -3.4e38f, denom = 0.f;
    float4 acc = make_float4(0.f, 0.f, 0.f, 0.f);

    for (int e = start; e < end; e++) {
        int s = g_src[e];
        float4 xv = *(const float4*)(xl + (size_t)s * HC + col);
        float t0 = xv.x + xr4.x;
        float t1 = xv.y + xr4.y;
        float t2 = xv.z + xr4.z;
        float t3 = xv.w + xr4.w;
        t0 = t0 > 0.f ? t0 : 0.2f * t0;
        t1 = t1 > 0.f ? t1 : 0.2f * t1;
        t2 = t2 > 0.f ? t2 : 0.2f * t2;
        t3 = t3 > 0.f ? t3 : 0.2f * t3;
        float p = t0 * a4.x + t1 * a4.y + t2 * a4.z + t3 * a4.w;
#pragma unroll
        for (int o = 16; o; o >>= 1) p += __shfl_xor_sync(0xffffffffu, p, o);
        if (lane == 0) alpha[(size_t)g_eid[e] * HH + h] = p;  // park raw logit
        if (p > m) {
            float sc = __expf(m - p);
            denom *= sc;
            acc.x *= sc; acc.y *= sc; acc.z *= sc; acc.w *= sc;
            m = p;
        }
        float ex = __expf(p - m);
        denom += ex;
        acc.x += ex * xv.x;
        acc.y += ex * xv.y;
        acc.z += ex * xv.z;
        acc.w += ex * xv.w;
    }
    float inv = 1.f / (denom + 1e-16f);
    __syncwarp();
    for (int e = start + lane; e < end; e += 32) {
        size_t idx = (size_t)g_eid[e] * HH + h;
        alpha[idx] = __expf(alpha[idx] - m) * inv;
    }

    __shared__ float red[HC];
    red[col + 0] = acc.x * inv;
    red[col + 1] = acc.y * inv;
    red[col + 2] = acc.z * inv;
    red[col + 3] = acc.w * inv;
    __syncthreads();
    float sum = (red[t] + red[CC + t] + red[2 * CC + t] + red[3 * CC + t]) * 0.25f + bias[t];
    float scale = bng[t] * rsqrtf(bnv[t] + 1e-5f);
    float y = (sum - bnm[t]) * scale + bnb[t];
    y = fmaxf(y, 0.f);

    if (LAYER == 1) {
        g_h[(size_t)i * CC + t] = y;
    } else {
        __shared__ float rr[CC];
        rr[t] = y * Wlin[t];
        __syncthreads();
#pragma unroll
        for (int o = 64; o; o >>= 1) {
            if (t < o) rr[t] += rr[t + o];
            __syncthreads();
        }
        if (t == 0) {
            float z = fmaxf(rr[0] + blin[0], 0.f);
            nodeout[i] = 1.f / (1.f + __expf(-z));
        }
    }
}

// ---------------- launch ----------------
extern "C" void kernel_launch(void* const* d_in, const int* in_sizes, int n_in,
                              void* d_out, int out_size) {
    const float* x = (const float*)d_in[0];
    const void* ei = d_in[1];
    const float* Wl1 = (const float*)d_in[2];
    const float* Wr1 = (const float*)d_in[3];
    const float* att1 = (const float*)d_in[4];
    const float* b1 = (const float*)d_in[5];
    const float* Wl2 = (const float*)d_in[6];
    const float* Wr2 = (const float*)d_in[7];
    const float* att2 = (const float*)d_in[8];
    const float* b2 = (const float*)d_in[9];
    const float* g1 = (const float*)d_in[10];
    const float* be1 = (const float*)d_in[11];
    const float* m1 = (const float*)d_in[12];
    const float* v1 = (const float*)d_in[13];
    const float* g2 = (const float*)d_in[14];
    const float* be2 = (const float*)d_in[15];
    const float* m2 = (const float*)d_in[16];
    const float* v2 = (const float*)d_in[17];
    const float* Wlin = (const float*)d_in[18];
    const float* blin = (const float*)d_in[19];

    float* out = (float*)d_out;
    float* alpha1 = out + NN;
    float* alpha2 = alpha1 + (size_t)EP * HH;

    detect_dtype<<<1, 1>>>((const unsigned int*)ei);
    init_deg<<<(NN + 255) / 256, 256>>>();
    count_deg<<<(EE + 255) / 256, 256>>>(ei);
    scan_off<<<1, 1024>>>();
    fill_csr<<<(EP + 255) / 256, 256>>>(ei);

    dim3 gg(HC / 64, (NN + 127) / 128, 2);
    gemm_tf32<0, INC><<<gg, 256>>>(x, Wl1, Wr1);
    edge_attn<1><<<NN, 128>>>(att1, b1, g1, be1, m1, v1,
                              nullptr, nullptr, alpha1, nullptr);
    gemm_tf32<1, CC><<<gg, 256>>>(nullptr, Wl2, Wr2);
    edge_attn<2><<<NN, 128>>>(att2, b2, g2, be2, m2, v2,
                              Wlin, blin, alpha2, out);
}